// round 1
// baseline (speedup 1.0000x reference)
#include <cuda_runtime.h>
#include <math.h>

// ----------------------------------------------------------------------------
// BaseModel_81509889344081: margin ranking loss (all i<j pairs) + weighted BCE.
//
// Analytic decomposition (labels are {0,1}):
//   pairs with equal labels:   prod = 0            -> contribute relu(m) = m each
//   pairs with mixed labels:   prod = p_pos-p_neg  -> contribute relu(m - p_pos + p_neg)
// margin_loss = [ m*(C(n0,2)+C(n1,2)) + sum_{a in pos, b in neg} relu(m - a + b) ] / B
// ----------------------------------------------------------------------------

#define K1_T      1024
#define K2_T      256
#define MAXB      8192
#define NEG_SPLIT 8
#define TILE      1024

// scratch (allocation-free rule: __device__ globals)
__device__ float    g_pos[MAXB];
__device__ float    g_neg[MAXB];
__device__ int      g_n1;
__device__ double   g_mixed;
__device__ unsigned g_done;

__device__ __forceinline__ float read_margin(const void* p) {
    if (p == nullptr) return 1.0f;
    int v = *(const int*)p;
    // int scalar (small magnitude) vs float32 bit pattern heuristic
    if (v >= -1000000 && v <= 1000000) return (float)v;
    return __int_as_float(v);
}

// ---------------------------------------------------------------------------
// Kernel 1: single block. Deterministic partition of preds by label via block
// scan, BCE reduction, accumulator reset.
// ---------------------------------------------------------------------------
__global__ void k1_partition_bce(const float* __restrict__ preds,
                                 const float* __restrict__ labels,
                                 const float* __restrict__ logits,
                                 const float* __restrict__ targets,
                                 const float* __restrict__ pos_weight,
                                 int n, float* __restrict__ out)
{
    const int tid = threadIdx.x;
    const int T   = K1_T;

    if (tid == 0) { g_mixed = 0.0; g_done = 0u; }

    const int chunk = (n + T - 1) / T;      // 8 for B=8192
    const int s = tid * chunk;
    const int e = min(s + chunk, n);

    // per-thread positive count + BCE partial
    const float pw = pos_weight[0];
    int cp = 0;
    double bce = 0.0;
    for (int i = s; i < e; i++) {
        cp += (labels[i] > 0.5f) ? 1 : 0;
        const float x = logits[i];
        const float t = targets[i];
        const float mv = fmaxf(-x, 0.0f);
        const float lw = 1.0f + (pw - 1.0f) * t;
        const float term = (1.0f - t) * x
                         + lw * (logf(expf(-mv) + expf(-x - mv)) + mv);
        bce += (double)term;
    }

    // Hillis-Steele inclusive scan of positive counts (deterministic partition)
    __shared__ int scan[K1_T];
    scan[tid] = cp;
    __syncthreads();
    for (int off = 1; off < T; off <<= 1) {
        int v = (tid >= off) ? scan[tid - off] : 0;
        __syncthreads();
        scan[tid] += v;
        __syncthreads();
    }
    const int incl    = scan[tid];
    const int posBase = incl - cp;                 // exclusive prefix
    const int negBase = min(s, n) - posBase;       // negatives before my chunk
    const int total1  = scan[T - 1];
    if (tid == 0) g_n1 = total1;
    __syncthreads();

    // scatter preds into pos/neg scratch
    {
        int pi = posBase, ni = negBase;
        for (int i = s; i < e; i++) {
            const float p = preds[i];
            if (labels[i] > 0.5f) g_pos[pi++] = p;
            else                  g_neg[ni++] = p;
        }
    }

    // BCE block reduction (fp64)
    __shared__ double sd[K1_T];
    sd[tid] = bce;
    __syncthreads();
    for (int off = T >> 1; off > 0; off >>= 1) {
        if (tid < off) sd[tid] += sd[tid + off];
        __syncthreads();
    }
    if (tid == 0) out[1] = (float)(sd[0] / (double)n);
}

// ---------------------------------------------------------------------------
// Kernel 2: mixed-pair sum. blockIdx.x tiles pos (1 value/thread in a
// register); blockIdx.y splits neg range; neg streamed through smem tiles.
// Last block folds in the closed-form equal-label term and writes out[0].
// ---------------------------------------------------------------------------
__global__ void k2_pairs(int n, const void* __restrict__ margin_ptr,
                         float* __restrict__ out)
{
    const int tid = threadIdx.x;
    const float m = read_margin(margin_ptr);

    const int n1 = g_n1;
    const int n0 = n - n1;

    const int  pidx  = blockIdx.x * K2_T + tid;
    const bool valid = (pidx < n1);
    const float a    = valid ? g_pos[pidx] : 0.0f;

    // neg sub-range for this y-slice
    const int nchunk = (n0 + NEG_SPLIT - 1) / NEG_SPLIT;
    const int ns = blockIdx.y * nchunk;
    const int ne = min(ns + nchunk, n0);

    __shared__ float tile[TILE];
    double accd = 0.0;

    for (int base = ns; base < ne; base += TILE) {
        const int cnt = min(TILE, ne - base);
        for (int i = tid; i < cnt; i += K2_T)
            tile[i] = m + g_neg[base + i];          // precompute (m + b)
        __syncthreads();

        if (valid) {
            float acc = 0.0f;                        // <=1024 terms: fp32 safe
            int i = 0;
            #pragma unroll 4
            for (; i + 4 <= cnt; i += 4) {
                acc += fmaxf(tile[i]     - a, 0.0f);
                acc += fmaxf(tile[i + 1] - a, 0.0f);
                acc += fmaxf(tile[i + 2] - a, 0.0f);
                acc += fmaxf(tile[i + 3] - a, 0.0f);
            }
            for (; i < cnt; i++) acc += fmaxf(tile[i] - a, 0.0f);
            accd += (double)acc;
        }
        __syncthreads();
    }

    // block reduction in fp64
    __shared__ double red[K2_T];
    red[tid] = accd;
    __syncthreads();
    for (int off = K2_T >> 1; off > 0; off >>= 1) {
        if (tid < off) red[tid] += red[tid + off];
        __syncthreads();
    }
    if (tid == 0) {
        atomicAdd(&g_mixed, red[0]);
        __threadfence();
        const unsigned prev  = atomicAdd(&g_done, 1u);
        const unsigned total = gridDim.x * gridDim.y;
        if (prev == total - 1) {
            const double dn1 = (double)n1, dn0 = (double)n0;
            const double eqPairs = 0.5 * (dn1 * (dn1 - 1.0) + dn0 * (dn0 - 1.0));
            const double eqContrib = (m > 0.0f) ? (double)m * eqPairs : 0.0;
            out[0] = (float)((eqContrib + g_mixed) / (double)n);
        }
    }
}

// ---------------------------------------------------------------------------
extern "C" void kernel_launch(void* const* d_in, const int* in_sizes, int n_in,
                              void* d_out, int out_size)
{
    const float* preds   = (const float*)d_in[0];
    const float* labels  = (const float*)d_in[1];
    const float* logits  = (const float*)d_in[2];
    const float* targets = (const float*)d_in[3];
    const float* pw      = (const float*)d_in[4];
    const void*  marginp = (n_in >= 6) ? d_in[5] : nullptr;
    const int n = in_sizes[0];
    float* out = (float*)d_out;

    k1_partition_bce<<<1, K1_T>>>(preds, labels, logits, targets, pw, n, out);

    dim3 grid((n + K2_T - 1) / K2_T, NEG_SPLIT);
    k2_pairs<<<grid, K2_T>>>(n, marginp, out);
}